// round 2
// baseline (speedup 1.0000x reference)
#include <cuda_runtime.h>

#define MAXN 50000
#define D 128
#define BM 128
#define BK 32
#define BMP 132   // padded As stride (keeps 16B alignment, reduces STS conflicts)

typedef unsigned long long ull;

// Scratch (no cudaMalloc allowed)
__device__ float g_buf0[MAXN * D];   // aggregated input, later h2 raw
__device__ float g_buf1[MAXN * D];   // h1 raw
__device__ float g_sum[2][D];
__device__ float g_sq[2][D];
__device__ float g_scale[2][D];
__device__ float g_shift[2][D];
__device__ int   g_is64;

// ---------------------------------------------------------------------------
__device__ __forceinline__ ull pack2(float x, float y) {
    ull d;
    asm("mov.b64 %0, {%1, %2};" : "=l"(d) : "f"(x), "f"(y));
    return d;
}
__device__ __forceinline__ void unpack2(ull d, float& x, float& y) {
    asm("mov.b64 {%0, %1}, %2;" : "=f"(x), "=f"(y) : "l"(d));
}
__device__ __forceinline__ void fma2(ull& d, ull a, ull b) {
    asm("fma.rn.f32x2 %0, %1, %2, %0;" : "+l"(d) : "l"(a), "l"(b));
}

// ---------------------------------------------------------------------------
// Detect int64 vs int32 edge_index (JAX x64 ambiguity).
__global__ void detect_kernel(const long long* __restrict__ ei, int E, int N) {
    __shared__ int bad;
    if (threadIdx.x == 0) bad = 0;
    __syncthreads();
    int M = min(E, 4096);
    for (int i = threadIdx.x; i < M; i += blockDim.x) {
        long long v = ei[i];
        if (v < 0 || v >= (long long)N) bad = 1;
    }
    __syncthreads();
    if (threadIdx.x == 0) g_is64 = bad ? 0 : 1;
}

// ---------------------------------------------------------------------------
// g_buf0 = (1+eps)*x ; zero stats accumulators
__global__ void init_kernel(const float* __restrict__ x,
                            const float* __restrict__ eps, int total4) {
    int i = blockIdx.x * blockDim.x + threadIdx.x;
    float s = 1.0f + eps[0];
    if (i < total4) {
        float4 v = ((const float4*)x)[i];
        v.x *= s; v.y *= s; v.z *= s; v.w *= s;
        ((float4*)g_buf0)[i] = v;
    }
    if (blockIdx.x == 0 && threadIdx.x < 2 * D) {
        int p = threadIdx.x / D, c = threadIdx.x % D;
        g_sum[p][c] = 0.f;
        g_sq[p][c]  = 0.f;
    }
}

// ---------------------------------------------------------------------------
// One warp per edge: gather x[src] row, vector-reduce into g_buf0[dst].
__global__ void scatter_kernel(const float* __restrict__ x,
                               const void* __restrict__ ei_raw, int E) {
    int e = (blockIdx.x * blockDim.x + threadIdx.x) >> 5;
    if (e >= E) return;
    int lane = threadIdx.x & 31;
    long long s, d;
    if (g_is64) {
        const long long* p = (const long long*)ei_raw;
        s = p[e];
        d = p[E + e];
    } else {
        const int* p = (const int*)ei_raw;
        s = p[e];
        d = p[E + e];
    }
    float4 v = __ldg((const float4*)(x + s * D) + lane);
    float* addr = g_buf0 + d * D + (lane << 2);
    asm volatile("red.global.add.v4.f32 [%0], {%1,%2,%3,%4};"
                 :: "l"(addr), "f"(v.x), "f"(v.y), "f"(v.z), "f"(v.w)
                 : "memory");
}

// ---------------------------------------------------------------------------
// out[N,128] = op(A)[N,128] @ W[128,128] + bias, fused with:
//   - optional input normalization (normPhase >= 0): a = relu(a*scale+shift)
//   - BN stats accumulation (column sum / sumsq of output) into g_sum/g_sq[phase]
// Tile: 128x128, BK=32, 256 threads, 8x8 per thread via packed f32x2 FMA.
__global__ void __launch_bounds__(256, 2)
gemm_kernel(const float* __restrict__ A, const float* __restrict__ W,
            const float* __restrict__ bias, float* __restrict__ out,
            int N, int phase, int normPhase) {
    __shared__ __align__(16) float As[BK][BMP];
    __shared__ __align__(16) float Bs[BK][D];

    int tid = threadIdx.x;
    int tx = tid & 15;        // col group: cols tx*8 .. tx*8+7
    int ty = tid >> 4;        // row group: rows ty*8 .. ty*8+7
    int rowStart = blockIdx.x * BM;

    ull acc[8][4];
#pragma unroll
    for (int i = 0; i < 8; i++)
#pragma unroll
        for (int p = 0; p < 4; p++) acc[i][p] = 0ull;

    for (int kc = 0; kc < D; kc += BK) {
        // Load A tile (128x32 = 1024 float4, 4 per thread), transpose into As
#pragma unroll
        for (int l = 0; l < 4; l++) {
            int t   = tid + 256 * l;
            int row = t >> 3;        // 0..127
            int c4  = t & 7;         // k offset c4*4
            int gr  = rowStart + row;
            float4 v = make_float4(0.f, 0.f, 0.f, 0.f);
            if (gr < N) v = ((const float4*)(A + (size_t)gr * D + kc))[c4];
            if (normPhase >= 0) {
                float4 sc = ((const float4*)g_scale[normPhase])[(kc >> 2) + c4];
                float4 sh = ((const float4*)g_shift[normPhase])[(kc >> 2) + c4];
                v.x = fmaxf(v.x * sc.x + sh.x, 0.f);
                v.y = fmaxf(v.y * sc.y + sh.y, 0.f);
                v.z = fmaxf(v.z * sc.z + sh.z, 0.f);
                v.w = fmaxf(v.w * sc.w + sh.w, 0.f);
            }
            As[c4 * 4 + 0][row] = v.x;
            As[c4 * 4 + 1][row] = v.y;
            As[c4 * 4 + 2][row] = v.z;
            As[c4 * 4 + 3][row] = v.w;
        }
        // Load B tile (32x128 = 1024 float4, 4 per thread)
#pragma unroll
        for (int l = 0; l < 4; l++) {
            int t   = tid + 256 * l;
            int row = t >> 5;
            int c4  = t & 31;
            *((float4*)&Bs[row][c4 * 4]) =
                ((const float4*)(W + (size_t)(kc + row) * D))[c4];
        }
        __syncthreads();

#pragma unroll
        for (int kk = 0; kk < BK; kk++) {
            float4 a0 = *((const float4*)&As[kk][ty * 8]);
            float4 a1 = *((const float4*)&As[kk][ty * 8 + 4]);
            ull bb[4];
#pragma unroll
            for (int p = 0; p < 4; p++)
                bb[p] = *((const ull*)&Bs[kk][tx * 8 + 2 * p]);
            float a[8] = {a0.x, a0.y, a0.z, a0.w, a1.x, a1.y, a1.z, a1.w};
#pragma unroll
            for (int i = 0; i < 8; i++) {
                ull aa = pack2(a[i], a[i]);
#pragma unroll
                for (int p = 0; p < 4; p++) fma2(acc[i][p], aa, bb[p]);
            }
        }
        __syncthreads();
    }

    // Epilogue: bias, store, column stats from registers
    float4 bb0 = ((const float4*)bias)[tx * 2];
    float4 bb1 = ((const float4*)bias)[tx * 2 + 1];
    float bcol[8] = {bb0.x, bb0.y, bb0.z, bb0.w, bb1.x, bb1.y, bb1.z, bb1.w};
    float s[8], q[8];
#pragma unroll
    for (int j = 0; j < 8; j++) { s[j] = 0.f; q[j] = 0.f; }

#pragma unroll
    for (int i = 0; i < 8; i++) {
        int gr = rowStart + ty * 8 + i;
        if (gr < N) {
            float h[8];
#pragma unroll
            for (int p = 0; p < 4; p++)
                unpack2(acc[i][p], h[2 * p], h[2 * p + 1]);
#pragma unroll
            for (int j = 0; j < 8; j++) {
                h[j] += bcol[j];
                s[j] += h[j];
                q[j] += h[j] * h[j];
            }
            float* o = out + (size_t)gr * D + tx * 8;
            *((float4*)o)       = make_float4(h[0], h[1], h[2], h[3]);
            *((float4*)(o + 4)) = make_float4(h[4], h[5], h[6], h[7]);
        }
    }
    // halve atomic count: combine ty-even/odd lanes (lane xor 16)
#pragma unroll
    for (int j = 0; j < 8; j++) {
        s[j] += __shfl_xor_sync(0xffffffffu, s[j], 16);
        q[j] += __shfl_xor_sync(0xffffffffu, q[j], 16);
    }
    if ((ty & 1) == 0) {
#pragma unroll
        for (int j = 0; j < 8; j++) {
            atomicAdd(&g_sum[phase][tx * 8 + j], s[j]);
            atomicAdd(&g_sq[phase][tx * 8 + j],  q[j]);
        }
    }
}

// ---------------------------------------------------------------------------
__global__ void finalize_kernel(int phase, const float* __restrict__ g,
                                const float* __restrict__ beta, float invN) {
    int c = threadIdx.x;
    float mu  = g_sum[phase][c] * invN;
    float var = g_sq[phase][c] * invN - mu * mu;
    float inv = rsqrtf(var + 1e-5f);
    float sc  = g[c] * inv;
    g_scale[phase][c] = sc;
    g_shift[phase][c] = beta[c] - mu * sc;
}

// ---------------------------------------------------------------------------
// out = relu(h*scale + shift)  (final layer -> d_out)
__global__ void norm_kernel(const float* __restrict__ h, int phase,
                            float* __restrict__ extout, int total4) {
    int i = blockIdx.x * blockDim.x + threadIdx.x;
    if (i >= total4) return;
    int c4 = i & 31;
    float4 v  = ((const float4*)h)[i];
    float4 sc = ((const float4*)g_scale[phase])[c4];
    float4 sh = ((const float4*)g_shift[phase])[c4];
    float4 o;
    o.x = fmaxf(v.x * sc.x + sh.x, 0.f);
    o.y = fmaxf(v.y * sc.y + sh.y, 0.f);
    o.z = fmaxf(v.z * sc.z + sh.z, 0.f);
    o.w = fmaxf(v.w * sc.w + sh.w, 0.f);
    ((float4*)extout)[i] = o;
}

// ---------------------------------------------------------------------------
extern "C" void kernel_launch(void* const* d_in, const int* in_sizes, int n_in,
                              void* d_out, int out_size) {
    const float* x   = (const float*)d_in[0];
    const void*  ei  = d_in[1];
    const float* eps = (const float*)d_in[2];
    const float* W1  = (const float*)d_in[3];
    const float* b1  = (const float*)d_in[4];
    const float* g1  = (const float*)d_in[5];
    const float* be1 = (const float*)d_in[6];
    const float* W2  = (const float*)d_in[7];
    const float* b2  = (const float*)d_in[8];
    const float* g2  = (const float*)d_in[9];
    const float* be2 = (const float*)d_in[10];

    int N = in_sizes[0] / D;
    int E = in_sizes[1] / 2;
    int total4 = N * (D / 4);
    const int TB = 256;

    float* buf0;
    float* buf1;
    cudaGetSymbolAddress((void**)&buf0, g_buf0);
    cudaGetSymbolAddress((void**)&buf1, g_buf1);

    detect_kernel<<<1, 256>>>((const long long*)ei, E, N);
    init_kernel<<<(total4 + TB - 1) / TB, TB>>>(x, eps, total4);

    long long sthreads = (long long)E * 32;
    scatter_kernel<<<(unsigned)((sthreads + TB - 1) / TB), TB>>>(x, ei, E);

    int gblocks = (N + BM - 1) / BM;
    float invN = 1.0f / (float)N;

    // layer 1: h1 = g_buf0 @ W1 + b1  (stats fused)
    gemm_kernel<<<gblocks, 256>>>(buf0, W1, b1, buf1, N, 0, -1);
    finalize_kernel<<<1, D>>>(0, g1, be1, invN);
    // layer 2: h2 = relu(bn(h1)) @ W2 + b2  (norm of h1 fused into A-load)
    gemm_kernel<<<gblocks, 256>>>(buf1, W2, b2, buf0, N, 1, 0);
    finalize_kernel<<<1, D>>>(1, g2, be2, invN);
    // final: d_out = relu(bn(h2))
    norm_kernel<<<(total4 + TB - 1) / TB, TB>>>(buf0, 1, (float*)d_out, total4);
}